// round 1
// baseline (speedup 1.0000x reference)
#include <cuda_runtime.h>
#include <math.h>

// Problem constants (match setup_inputs)
#define BB 2
#define NN 512
#define CC 256
#define OUTSZ 14
#define SS 28           // OUT * RATIO
#define POOL_PER_BOX (CC * OUTSZ * OUTSZ)   // 50176
#define NMS_THRC 0.5f

// Scratch (no allocations allowed)
__device__ float g_verts[BB * NN * 4];
__device__ int   g_level[BB * NN];
__device__ int   g_keep [BB * NN];

// ---------------------------------------------------------------------------
// Kernel 1: per-batch NMS. One block of 512 threads per batch.
// Computes verts + level, bitonic-sorts by (-score, idx) (stable argsort
// equivalence), runs greedy suppression, writes keep in original order.
// ---------------------------------------------------------------------------
__global__ __launch_bounds__(NN) void nms_kernel(const float* __restrict__ boxes,
                                                 const float* __restrict__ scores)
{
    const int b   = blockIdx.x;
    const int tid = threadIdx.x;

    __shared__ float skey[NN];
    __shared__ int   sidx[NN];
    __shared__ float bx1[NN], by1[NN], bx2[NN], by2[NN], barea[NN];
    __shared__ int   slev[NN];
    __shared__ unsigned char keep_s[NN];

    // --- verts + level ---
    const float* bb = boxes + (size_t)b * NN * 4;
    float cx = bb[tid * 4 + 0];
    float cy = bb[tid * 4 + 1];
    float w  = bb[tid * 4 + 2];
    float h  = bb[tid * 4 + 3];
    float x1 = cx - w * 0.5f;
    float y1 = cy - h * 0.5f;
    float x2 = cx + w * 0.5f;
    float y2 = cy + h * 0.5f;

    float lv = floorf(3.0f + log2f(sqrtf(w * h) / 224.0f));
    lv = fminf(fmaxf(lv, 1.0f), 4.0f);
    int lev = (int)lv;

    int gi = b * NN + tid;
    g_verts[gi * 4 + 0] = x1;
    g_verts[gi * 4 + 1] = y1;
    g_verts[gi * 4 + 2] = x2;
    g_verts[gi * 4 + 3] = y2;
    g_level[gi] = lev;

    skey[tid] = scores[gi];
    sidx[tid] = tid;
    __syncthreads();

    // --- bitonic sort: final order = descending score, ties by ascending idx ---
    for (int k = 2; k <= NN; k <<= 1) {
        for (int j = k >> 1; j > 0; j >>= 1) {
            int ixj = tid ^ j;
            if (ixj > tid) {
                float sa = skey[tid], sb2 = skey[ixj];
                int   ia = sidx[tid], ib  = sidx[ixj];
                // "a_first": element a belongs before b in the final order
                bool a_first = (sa > sb2) || (sa == sb2 && ia < ib);
                bool ascending = ((tid & k) == 0);
                // ascending segment wants a_first == true at (tid, ixj); swap if not
                bool do_swap = ascending ? (!a_first) : a_first;
                if (do_swap) {
                    skey[tid] = sb2; skey[ixj] = sa;
                    sidx[tid] = ib;  sidx[ixj] = ia;
                }
            }
            __syncthreads();
        }
    }

    // --- load sorted boxes ---
    int o = sidx[tid];
    int go = b * NN + o;
    float sx1 = g_verts[go * 4 + 0];
    float sy1 = g_verts[go * 4 + 1];
    float sx2 = g_verts[go * 4 + 2];
    float sy2 = g_verts[go * 4 + 3];
    bx1[tid] = sx1; by1[tid] = sy1; bx2[tid] = sx2; by2[tid] = sy2;
    barea[tid] = (sx2 - sx1) * (sy2 - sy1);
    slev[tid]  = g_level[go];
    keep_s[tid] = 1;
    __syncthreads();

    float my_x1 = sx1, my_y1 = sy1, my_x2 = sx2, my_y2 = sy2;
    float my_area = barea[tid];
    int   my_lev  = slev[tid];

    // --- greedy suppression (sequential over sorted ranks) ---
    for (int i = 0; i < NN - 1; i++) {
        __syncthreads();
        if (tid > i && keep_s[tid] && keep_s[i] && my_lev == slev[i]) {
            float ix1 = fmaxf(my_x1, bx1[i]);
            float iy1 = fmaxf(my_y1, by1[i]);
            float ix2 = fminf(my_x2, bx2[i]);
            float iy2 = fminf(my_y2, by2[i]);
            float iw = fmaxf(ix2 - ix1, 0.0f);
            float ih = fmaxf(iy2 - iy1, 0.0f);
            float inter = iw * ih;
            float iou = inter / (my_area + barea[i] - inter + 1e-9f);
            if (iou > NMS_THRC) keep_s[tid] = 0;
        }
    }
    __syncthreads();
    g_keep[b * NN + o] = keep_s[tid];
}

// ---------------------------------------------------------------------------
// Kernel 2: ROI align pooling. One 256-thread block per (b, n) box.
// Separable sample tables in shared; zero-fill for non-kept boxes.
// ---------------------------------------------------------------------------
__global__ __launch_bounds__(256) void pool_kernel(const float* __restrict__ p4,
                                                   const float* __restrict__ p8,
                                                   const float* __restrict__ p16,
                                                   const float* __restrict__ p32,
                                                   float* __restrict__ out)
{
    const int bn  = blockIdx.x;       // 0 .. B*N-1
    const int b   = bn / NN;
    const int tid = threadIdx.x;

    float* o = out + (size_t)bn * POOL_PER_BOX;

    if (!g_keep[bn]) {
        // zero-fill 50176 floats = 12544 float4
        float4* o4 = (float4*)o;
        float4 z = make_float4(0.f, 0.f, 0.f, 0.f);
        #pragma unroll 4
        for (int i = tid; i < POOL_PER_BOX / 4; i += 256) o4[i] = z;
        return;
    }

    const int lev = g_level[bn];
    const float* feat;
    int H;
    float stride;
    if (lev == 1)      { feat = p4;  H = 256; stride = 4.0f;  }
    else if (lev == 2) { feat = p8;  H = 128; stride = 8.0f;  }
    else if (lev == 3) { feat = p16; H = 64;  stride = 16.0f; }
    else               { feat = p32; H = 32;  stride = 32.0f; }
    const int W = H;

    __shared__ int   sxi0[SS], sxi1[SS], syi0[SS], syi1[SS];
    __shared__ float slxA[SS], slyA[SS];

    // ROI in feature coords
    float rx1 = g_verts[bn * 4 + 0] / stride;
    float ry1 = g_verts[bn * 4 + 1] / stride;
    float rx2 = g_verts[bn * 4 + 2] / stride;
    float ry2 = g_verts[bn * 4 + 3] / stride;
    float bw = (rx2 - rx1) / (float)OUTSZ;
    float bh = (ry2 - ry1) / (float)OUTSZ;

    if (tid < SS) {
        float g = ((float)tid + 0.5f) / 2.0f;       // RATIO = 2
        float xs = rx1 + g * bw;
        xs = fminf(fmaxf(xs, 0.0f), (float)W - 1.0f);
        float x0 = floorf(xs);
        int x0i = (int)x0;
        sxi0[tid] = x0i;
        sxi1[tid] = min(x0i + 1, W - 1);
        slxA[tid] = xs - x0;
    } else if (tid < 2 * SS) {
        int t = tid - SS;
        float g = ((float)t + 0.5f) / 2.0f;
        float ys = ry1 + g * bh;
        ys = fminf(fmaxf(ys, 0.0f), (float)H - 1.0f);
        float y0 = floorf(ys);
        int y0i = (int)y0;
        syi0[t] = y0i;
        syi1[t] = min(y0i + 1, H - 1);
        slyA[t] = ys - y0;
    }
    __syncthreads();

    const float* fb = feat + (size_t)b * CC * H * W;

    for (int idx = tid; idx < POOL_PER_BOX; idx += 256) {
        int c   = idx / (OUTSZ * OUTSZ);
        int pos = idx - c * (OUTSZ * OUTSZ);
        int oy  = pos / OUTSZ;
        int ox  = pos - oy * OUTSZ;

        const float* fc = fb + (size_t)c * H * W;
        float acc = 0.0f;
        #pragma unroll
        for (int dy = 0; dy < 2; dy++) {
            int yy = 2 * oy + dy;
            int y0 = syi0[yy], y1 = syi1[yy];
            float ly = slyA[yy];
            const float* r0 = fc + (size_t)y0 * W;
            const float* r1 = fc + (size_t)y1 * W;
            #pragma unroll
            for (int dx = 0; dx < 2; dx++) {
                int xx = 2 * ox + dx;
                int x0 = sxi0[xx], x1 = sxi1[xx];
                float lx = slxA[xx];
                float v00 = __ldg(r0 + x0);
                float v01 = __ldg(r0 + x1);
                float v10 = __ldg(r1 + x0);
                float v11 = __ldg(r1 + x1);
                acc += v00 * (1.0f - ly) * (1.0f - lx)
                     + v01 * (1.0f - ly) * lx
                     + v10 * ly * (1.0f - lx)
                     + v11 * ly * lx;
            }
        }
        o[idx] = acc * 0.25f;
    }
}

// ---------------------------------------------------------------------------
// Kernel 3: out_boxes + keep tail of the output buffer.
// ---------------------------------------------------------------------------
__global__ void misc_kernel(float* __restrict__ out)
{
    int i = blockIdx.x * blockDim.x + threadIdx.x;
    if (i >= BB * NN) return;
    float* ob = out + (size_t)BB * NN * POOL_PER_BOX;   // out_boxes base
    float* ok = ob + (size_t)BB * NN * 4;               // keep base
    int k = g_keep[i];
    #pragma unroll
    for (int j = 0; j < 4; j++)
        ob[i * 4 + j] = k ? g_verts[i * 4 + j] : 0.0f;
    ok[i] = k ? 1.0f : 0.0f;
}

extern "C" void kernel_launch(void* const* d_in, const int* in_sizes, int n_in,
                              void* d_out, int out_size)
{
    const float* p4     = (const float*)d_in[0];
    const float* p8     = (const float*)d_in[1];
    const float* p16    = (const float*)d_in[2];
    const float* p32    = (const float*)d_in[3];
    const float* boxes  = (const float*)d_in[4];
    const float* scores = (const float*)d_in[5];
    float* out = (float*)d_out;

    nms_kernel<<<BB, NN>>>(boxes, scores);
    pool_kernel<<<BB * NN, 256>>>(p4, p8, p16, p32, out);

    // tail (out_boxes + keep) only if the output buffer includes it
    long long pooled = (long long)BB * NN * POOL_PER_BOX;
    if ((long long)out_size >= pooled + (long long)BB * NN * 5) {
        misc_kernel<<<(BB * NN + 255) / 256, 256>>>(out);
    }
}